// round 1
// baseline (speedup 1.0000x reference)
#include <cuda_runtime.h>
#include <math_constants.h>

namespace {
constexpr int kB = 2;
constexpr int kN = 2048;
constexpr int kDim = 1024;
constexpr int kH = 16;
constexpr int kD = 64;
constexpr int kTokens = kB * kN;          // 4096
constexpr float kScale = 0.125f;          // 1/sqrt(64)
}

// Scratch (device globals — no allocations allowed)
__device__ __align__(256) float g_xn[kTokens * kDim];        // layernormed x
__device__ __align__(256) float g_q[kB * kH * kN * kD];      // (b,h,n,d), pre-scaled
__device__ __align__(256) float g_k[kB * kH * kN * kD];
__device__ __align__(256) float g_v[kB * kH * kN * kD];
__device__ __align__(256) float g_attn[kTokens * kDim];      // (token, h*d)

// ---------------------------------------------------------------------------
// LayerNorm: one block per token, 256 threads, 4 elements (float4) each.
// ---------------------------------------------------------------------------
__global__ __launch_bounds__(256) void ln_kernel(const float* __restrict__ x,
                                                 const float* __restrict__ gamma,
                                                 const float* __restrict__ beta) {
    const int t = blockIdx.x;
    const int tid = threadIdx.x;
    const float4 xv = reinterpret_cast<const float4*>(x + (size_t)t * kDim)[tid];
    float s  = xv.x + xv.y + xv.z + xv.w;
    float ss = xv.x * xv.x + xv.y * xv.y + xv.z * xv.z + xv.w * xv.w;
    #pragma unroll
    for (int o = 16; o > 0; o >>= 1) {
        s  += __shfl_xor_sync(0xffffffffu, s, o);
        ss += __shfl_xor_sync(0xffffffffu, ss, o);
    }
    __shared__ float red_s[8], red_ss[8];
    if ((tid & 31) == 0) { red_s[tid >> 5] = s; red_ss[tid >> 5] = ss; }
    __syncthreads();
    float S = 0.f, SS = 0.f;
    #pragma unroll
    for (int i = 0; i < 8; i++) { S += red_s[i]; SS += red_ss[i]; }
    const float mu  = S * (1.0f / kDim);
    const float var = SS * (1.0f / kDim) - mu * mu;
    const float inv = rsqrtf(var + 1e-5f);
    const float4 g = reinterpret_cast<const float4*>(gamma)[tid];
    const float4 b = reinterpret_cast<const float4*>(beta)[tid];
    float4 out;
    out.x = (xv.x - mu) * inv * g.x + b.x;
    out.y = (xv.y - mu) * inv * g.y + b.y;
    out.z = (xv.z - mu) * inv * g.z + b.z;
    out.w = (xv.w - mu) * inv * g.w + b.w;
    reinterpret_cast<float4*>(g_xn + (size_t)t * kDim)[tid] = out;
}

// ---------------------------------------------------------------------------
// SGEMM: C[4096, Nw] = A[4096, 1024] @ B[1024, Nw]
// 128x128 block tile, K-tile 16, 256 threads, 8x8 register tile per thread.
// MODE 0: A=g_xn, scatter to g_q (cols 0..1023, *kScale) / g_k (cols 1024..2047)
// MODE 1: A=g_xn, scatter to g_v
// MODE 2: A=g_attn, C = A@B + bias -> out
// ---------------------------------------------------------------------------
template <int MODE>
__global__ __launch_bounds__(256) void sgemm128(const float* __restrict__ Bmat,
                                                float* __restrict__ out,
                                                const float* __restrict__ bias,
                                                int Nw) {
    const float* __restrict__ A = (MODE == 2) ? g_attn : g_xn;
    __shared__ float As[16][128];
    __shared__ float Bs[16][128];
    const int bm = blockIdx.y * 128;
    const int bn = blockIdx.x * 128;
    const int tid = threadIdx.x;
    const int ty = tid >> 4;   // M sub-tile 0..15
    const int tx = tid & 15;   // N sub-tile 0..15

    float acc[8][8];
    #pragma unroll
    for (int i = 0; i < 8; i++)
        #pragma unroll
        for (int j = 0; j < 8; j++) acc[i][j] = 0.f;

    for (int k0 = 0; k0 < kDim; k0 += 16) {
        // Load A tile [128 x 16], store transposed As[k][m]
        #pragma unroll
        for (int it = 0; it < 2; it++) {
            const int t = tid + it * 256;
            const int r = t >> 2;
            const int c4 = (t & 3) << 2;
            const float4 v = *reinterpret_cast<const float4*>(
                A + (size_t)(bm + r) * kDim + k0 + c4);
            As[c4 + 0][r] = v.x;
            As[c4 + 1][r] = v.y;
            As[c4 + 2][r] = v.z;
            As[c4 + 3][r] = v.w;
        }
        // Load B tile [16 x 128]
        #pragma unroll
        for (int it = 0; it < 2; it++) {
            const int t = tid + it * 256;
            const int r = t >> 5;
            const int c4 = (t & 31) << 2;
            *reinterpret_cast<float4*>(&Bs[r][c4]) =
                *reinterpret_cast<const float4*>(Bmat + (size_t)(k0 + r) * Nw + bn + c4);
        }
        __syncthreads();
        #pragma unroll
        for (int kk = 0; kk < 16; kk++) {
            const float4 a0 = *reinterpret_cast<const float4*>(&As[kk][ty * 8]);
            const float4 a1 = *reinterpret_cast<const float4*>(&As[kk][ty * 8 + 4]);
            const float4 b0 = *reinterpret_cast<const float4*>(&Bs[kk][tx * 8]);
            const float4 b1 = *reinterpret_cast<const float4*>(&Bs[kk][tx * 8 + 4]);
            const float a[8] = {a0.x, a0.y, a0.z, a0.w, a1.x, a1.y, a1.z, a1.w};
            const float b[8] = {b0.x, b0.y, b0.z, b0.w, b1.x, b1.y, b1.z, b1.w};
            #pragma unroll
            for (int i = 0; i < 8; i++)
                #pragma unroll
                for (int j = 0; j < 8; j++)
                    acc[i][j] = fmaf(a[i], b[j], acc[i][j]);
        }
        __syncthreads();
    }

    // Epilogue
    #pragma unroll
    for (int i = 0; i < 8; i++) {
        const int row = bm + ty * 8 + i;
        const int bidx = row >> 11;         // batch
        const int n = row & (kN - 1);       // seq position
        #pragma unroll
        for (int j = 0; j < 8; j++) {
            const int col = bn + tx * 8 + j;
            const float v = acc[i][j];
            if (MODE == 0) {
                if (col < kH * kD) {
                    const int h = col >> 6, d = col & 63;
                    g_q[(((size_t)(bidx * kH + h)) * kN + n) * kD + d] = v * kScale;
                } else {
                    const int c = col - kH * kD;
                    const int h = c >> 6, d = c & 63;
                    g_k[(((size_t)(bidx * kH + h)) * kN + n) * kD + d] = v;
                }
            } else if (MODE == 1) {
                const int h = col >> 6, d = col & 63;
                g_v[(((size_t)(bidx * kH + h)) * kN + n) * kD + d] = v;
            } else {
                out[(size_t)row * kDim + col] = v + bias[col];
            }
        }
    }
}

// ---------------------------------------------------------------------------
// Attention: grid (2048/128, b*h). One query row per thread, online softmax.
// K/V tiles (64 keys x 64 dims, fp32) staged in shared; broadcast LDS reads.
// q is pre-scaled by 1/sqrt(d).
// ---------------------------------------------------------------------------
__global__ __launch_bounds__(128) void attn_kernel() {
    const int bh = blockIdx.y;
    const int row = blockIdx.x * 128 + threadIdx.x;
    const float* __restrict__ Qp = g_q + (size_t)bh * kN * kD;
    const float* __restrict__ Kp = g_k + (size_t)bh * kN * kD;
    const float* __restrict__ Vp = g_v + (size_t)bh * kN * kD;

    __shared__ float Ks[64][64];
    __shared__ float Vs[64][64];

    float q[64], o[64];
    #pragma unroll
    for (int e4 = 0; e4 < 16; e4++) {
        const float4 qa = reinterpret_cast<const float4*>(Qp + (size_t)row * kD)[e4];
        q[e4 * 4 + 0] = qa.x;
        q[e4 * 4 + 1] = qa.y;
        q[e4 * 4 + 2] = qa.z;
        q[e4 * 4 + 3] = qa.w;
    }
    #pragma unroll
    for (int e = 0; e < 64; e++) o[e] = 0.f;
    float m = -CUDART_INF_F;
    float l = 0.f;

    for (int kt = 0; kt < kN; kt += 64) {
        __syncthreads();
        const float4* ksrc = reinterpret_cast<const float4*>(Kp + (size_t)kt * kD);
        const float4* vsrc = reinterpret_cast<const float4*>(Vp + (size_t)kt * kD);
        float4* kdst = reinterpret_cast<float4*>(&Ks[0][0]);
        float4* vdst = reinterpret_cast<float4*>(&Vs[0][0]);
        #pragma unroll
        for (int i = 0; i < 8; i++) {
            kdst[threadIdx.x + i * 128] = ksrc[threadIdx.x + i * 128];
            vdst[threadIdx.x + i * 128] = vsrc[threadIdx.x + i * 128];
        }
        __syncthreads();

        for (int j = 0; j < 64; j++) {
            const float4* kr = reinterpret_cast<const float4*>(&Ks[j][0]);
            float s = 0.f;
            #pragma unroll
            for (int e4 = 0; e4 < 16; e4++) {
                const float4 kv = kr[e4];
                s = fmaf(q[e4 * 4 + 0], kv.x, s);
                s = fmaf(q[e4 * 4 + 1], kv.y, s);
                s = fmaf(q[e4 * 4 + 2], kv.z, s);
                s = fmaf(q[e4 * 4 + 3], kv.w, s);
            }
            if (s > m) {
                const float corr = __expf(m - s);   // 0 on first key (m=-inf)
                m = s;
                l *= corr;
                #pragma unroll
                for (int e = 0; e < 64; e++) o[e] *= corr;
            }
            const float p = __expf(s - m);
            l += p;
            const float4* vr = reinterpret_cast<const float4*>(&Vs[j][0]);
            #pragma unroll
            for (int e4 = 0; e4 < 16; e4++) {
                const float4 vv = vr[e4];
                o[e4 * 4 + 0] = fmaf(p, vv.x, o[e4 * 4 + 0]);
                o[e4 * 4 + 1] = fmaf(p, vv.y, o[e4 * 4 + 1]);
                o[e4 * 4 + 2] = fmaf(p, vv.z, o[e4 * 4 + 2]);
                o[e4 * 4 + 3] = fmaf(p, vv.w, o[e4 * 4 + 3]);
            }
        }
    }

    const float invl = 1.0f / l;
    const int b = bh >> 4;
    const int h = bh & 15;
    float* dst = g_attn + ((size_t)(b * kN + row)) * kDim + h * kD;
    #pragma unroll
    for (int e4 = 0; e4 < 16; e4++) {
        float4 ov;
        ov.x = o[e4 * 4 + 0] * invl;
        ov.y = o[e4 * 4 + 1] * invl;
        ov.z = o[e4 * 4 + 2] * invl;
        ov.w = o[e4 * 4 + 3] * invl;
        reinterpret_cast<float4*>(dst)[e4] = ov;
    }
}

// ---------------------------------------------------------------------------
extern "C" void kernel_launch(void* const* d_in, const int* in_sizes, int n_in,
                              void* d_out, int out_size) {
    const float* x     = (const float*)d_in[0];
    const float* gamma = (const float*)d_in[1];
    const float* beta  = (const float*)d_in[2];
    const float* W_qk  = (const float*)d_in[3];
    const float* W_v   = (const float*)d_in[4];
    const float* W_out = (const float*)d_in[5];
    const float* b_out = (const float*)d_in[6];
    float* out = (float*)d_out;

    ln_kernel<<<kTokens, 256>>>(x, gamma, beta);
    sgemm128<0><<<dim3(2 * kH * kD / 128, kTokens / 128), 256>>>(W_qk, nullptr, nullptr, 2 * kH * kD);
    sgemm128<1><<<dim3(kH * kD / 128, kTokens / 128), 256>>>(W_v, nullptr, nullptr, kH * kD);
    attn_kernel<<<dim3(kN / 128, kB * kH), 128>>>();
    sgemm128<2><<<dim3(kDim / 128, kTokens / 128), 256>>>(W_out, out, b_out, kDim);
}

// round 3
// speedup vs baseline: 1.3272x; 1.3272x over previous
#include <cuda_runtime.h>
#include <math_constants.h>
#include <cstdint>

namespace {
constexpr int kB = 2;
constexpr int kN = 2048;
constexpr int kDim = 1024;
constexpr int kH = 16;
constexpr int kD = 64;
constexpr int kTokens = kB * kN;          // 4096
constexpr float kScale = 0.125f;          // 1/sqrt(64)
constexpr int kQKCols = 2 * kH * kD;      // 2048

constexpr int kPad = 36;                  // floats per smem row (conflict-free + 16B aligned)
constexpr int kStageFloats = 128 * kPad;  // one tile stage
constexpr int kGemmSmemBytes = 2 * 2 * kStageFloats * 4;  // 2 stages x (A+B) = 73728
}

// Scratch (device globals — no allocations allowed)
__device__ __align__(256) float g_xn[kTokens * kDim];        // layernormed x (tf32-rounded)
__device__ __align__(256) float g_q[kB * kH * kN * kD];      // (b,h,n,d), pre-scaled
__device__ __align__(256) float g_k[kB * kH * kN * kD];
__device__ __align__(256) float g_v[kB * kH * kN * kD];
__device__ __align__(256) float g_attn[kTokens * kDim];      // (token, h*d) tf32-rounded
__device__ __align__(256) float g_wqk_t[kQKCols * kDim];     // W_qk^T, tf32-rounded
__device__ __align__(256) float g_wv_t[kDim * kDim];
__device__ __align__(256) float g_wout_t[kDim * kDim];

// ---------------------------------------------------------------------------
// helpers
// ---------------------------------------------------------------------------
__device__ __forceinline__ float to_tf32(float x) {
    uint32_t u;
    asm("cvt.rna.tf32.f32 %0, %1;" : "=r"(u) : "f"(x));
    return __uint_as_float(u);
}

__device__ __forceinline__ uint32_t smem_u32(const void* p) {
    uint32_t a;
    asm("{ .reg .u64 t; cvta.to.shared.u64 t, %1; cvt.u32.u64 %0, t; }"
        : "=r"(a) : "l"(p));
    return a;
}

__device__ __forceinline__ void cp_async16(uint32_t dst, const void* src) {
    asm volatile("cp.async.cg.shared.global [%0], [%1], 16;" :: "r"(dst), "l"(src));
}
__device__ __forceinline__ void cp_commit() {
    asm volatile("cp.async.commit_group;");
}
template <int N> __device__ __forceinline__ void cp_wait() {
    asm volatile("cp.async.wait_group %0;" :: "n"(N));
}

// m16n8k8 tf32 mma: D += A@B, A row-major 16x8, B col-major 8x8, fp32 accum.
__device__ __forceinline__ void mma_tf32(float* c, const uint32_t* a, const uint32_t* b) {
    asm volatile(
        "mma.sync.aligned.m16n8k8.row.col.f32.tf32.tf32.f32 "
        "{%0,%1,%2,%3}, {%4,%5,%6,%7}, {%8,%9}, {%0,%1,%2,%3};"
        : "+f"(c[0]), "+f"(c[1]), "+f"(c[2]), "+f"(c[3])
        : "r"(a[0]), "r"(a[1]), "r"(a[2]), "r"(a[3]), "r"(b[0]), "r"(b[1]));
}

// ---------------------------------------------------------------------------
// LayerNorm: one block per token, 256 threads, float4 each; tf32-rounds output.
// ---------------------------------------------------------------------------
__global__ __launch_bounds__(256) void ln_kernel(const float* __restrict__ x,
                                                 const float* __restrict__ gamma,
                                                 const float* __restrict__ beta) {
    const int t = blockIdx.x;
    const int tid = threadIdx.x;
    const float4 xv = reinterpret_cast<const float4*>(x + (size_t)t * kDim)[tid];
    float s  = xv.x + xv.y + xv.z + xv.w;
    float ss = xv.x * xv.x + xv.y * xv.y + xv.z * xv.z + xv.w * xv.w;
    #pragma unroll
    for (int o = 16; o > 0; o >>= 1) {
        s  += __shfl_xor_sync(0xffffffffu, s, o);
        ss += __shfl_xor_sync(0xffffffffu, ss, o);
    }
    __shared__ float red_s[8], red_ss[8];
    if ((tid & 31) == 0) { red_s[tid >> 5] = s; red_ss[tid >> 5] = ss; }
    __syncthreads();
    float S = 0.f, SS = 0.f;
    #pragma unroll
    for (int i = 0; i < 8; i++) { S += red_s[i]; SS += red_ss[i]; }
    const float mu  = S * (1.0f / kDim);
    const float var = SS * (1.0f / kDim) - mu * mu;
    const float inv = rsqrtf(var + 1e-5f);
    const float4 g = reinterpret_cast<const float4*>(gamma)[tid];
    const float4 b = reinterpret_cast<const float4*>(beta)[tid];
    float4 out;
    out.x = to_tf32((xv.x - mu) * inv * g.x + b.x);
    out.y = to_tf32((xv.y - mu) * inv * g.y + b.y);
    out.z = to_tf32((xv.z - mu) * inv * g.z + b.z);
    out.w = to_tf32((xv.w - mu) * inv * g.w + b.w);
    reinterpret_cast<float4*>(g_xn + (size_t)t * kDim)[tid] = out;
}

// ---------------------------------------------------------------------------
// Transpose + tf32-round: src[rows][cols] -> dst[cols][rows]
// ---------------------------------------------------------------------------
__global__ __launch_bounds__(256) void transpose_tf32(const float* __restrict__ src,
                                                      float* __restrict__ dst,
                                                      int rows, int cols) {
    __shared__ float tile[32][33];
    const int bx = blockIdx.x * 32;   // col base
    const int by = blockIdx.y * 32;   // row base
    const int tx = threadIdx.x;
    #pragma unroll
    for (int i = threadIdx.y; i < 32; i += 8)
        tile[i][tx] = src[(size_t)(by + i) * cols + bx + tx];
    __syncthreads();
    #pragma unroll
    for (int i = threadIdx.y; i < 32; i += 8)
        dst[(size_t)(bx + i) * rows + by + tx] = to_tf32(tile[tx][i]);
}

// ---------------------------------------------------------------------------
// tf32 warp-MMA GEMM: C[4096 x Nw] = A[4096 x 1024] @ Bt^T  (Bt is [Nw x 1024])
// 128x128 CTA tile, 8 warps (2m x 4n, 64x32 each), K-tile 32, double-buffered
// cp.async. Fragment LDS from pad-36 smem (conflict-free).
// MODE 0: A=g_xn, Bt=W_qk^T  -> scatter q (x kScale) / k
// MODE 1: A=g_xn, Bt=W_v^T   -> scatter v
// MODE 2: A=g_attn, Bt=W_out^T -> out + bias
// ---------------------------------------------------------------------------
template <int MODE>
__global__ __launch_bounds__(256)
void gemm_mma(const float* __restrict__ Bt, float* __restrict__ outp,
              const float* __restrict__ bias) {
    extern __shared__ float smem_f[];
    const float* __restrict__ A = (MODE == 2) ? g_attn : g_xn;
    const int bm = blockIdx.y * 128;
    const int bn = blockIdx.x * 128;
    const int tid = threadIdx.x;
    const int wid = tid >> 5;
    const int lane = tid & 31;
    const int wm = wid & 1;            // 0..1
    const int wn = wid >> 1;           // 0..3
    const int m0 = wm * 64;
    const int n0 = wn * 32;

    float* sA[2] = {smem_f, smem_f + kStageFloats};
    float* sB[2] = {smem_f + 2 * kStageFloats, smem_f + 3 * kStageFloats};
    const uint32_t sAu[2] = {smem_u32(sA[0]), smem_u32(sA[1])};
    const uint32_t sBu[2] = {smem_u32(sB[0]), smem_u32(sB[1])};

    float acc[4][4][4];
    #pragma unroll
    for (int mi = 0; mi < 4; mi++)
        #pragma unroll
        for (int ni = 0; ni < 4; ni++)
            #pragma unroll
            for (int r = 0; r < 4; r++) acc[mi][ni][r] = 0.f;

    // stage loader: K offset t*32 -> stage s
    auto load_stage = [&](int t, int s) {
        const int k0 = t * 32;
        #pragma unroll
        for (int i = 0; i < 4; ++i) {
            const int idx = tid + i * 256;           // 0..1023
            const int r = idx >> 3;
            const int c4 = (idx & 7) << 2;           // 0,4,...,28
            cp_async16(sAu[s] + (uint32_t)(r * kPad + c4) * 4,
                       A + (size_t)(bm + r) * kDim + k0 + c4);
        }
        #pragma unroll
        for (int i = 0; i < 4; ++i) {
            const int idx = tid + i * 256;
            const int r = idx >> 3;
            const int c4 = (idx & 7) << 2;
            cp_async16(sBu[s] + (uint32_t)(r * kPad + c4) * 4,
                       Bt + (size_t)(bn + r) * kDim + k0 + c4);
        }
        cp_commit();
    };

    load_stage(0, 0);

    for (int t = 0; t < 32; ++t) {
        const int s = t & 1;
        if (t + 1 < 32) { load_stage(t + 1, s ^ 1); cp_wait<1>(); }
        else            { cp_wait<0>(); }
        __syncthreads();

        const float* As = sA[s];
        const float* Bs = sB[s];
        #pragma unroll
        for (int ks = 0; ks < 4; ++ks) {
            const int kc = ks * 8 + (lane & 3);
            uint32_t a[4][4], b[4][2];
            #pragma unroll
            for (int mi = 0; mi < 4; mi++) {
                const int r = m0 + mi * 16 + (lane >> 2);
                a[mi][0] = __float_as_uint(As[r * kPad + kc]);
                a[mi][1] = __float_as_uint(As[(r + 8) * kPad + kc]);
                a[mi][2] = __float_as_uint(As[r * kPad + kc + 4]);
                a[mi][3] = __float_as_uint(As[(r + 8) * kPad + kc + 4]);
            }
            #pragma unroll
            for (int ni = 0; ni < 4; ni++) {
                const int n = n0 + ni * 8 + (lane >> 2);
                b[ni][0] = __float_as_uint(Bs[n * kPad + kc]);
                b[ni][1] = __float_as_uint(Bs[n * kPad + kc + 4]);
            }
            #pragma unroll
            for (int mi = 0; mi < 4; mi++)
                #pragma unroll
                for (int ni = 0; ni < 4; ni++)
                    mma_tf32(acc[mi][ni], a[mi], b[ni]);
        }
        __syncthreads();
    }

    // ---- epilogue: fragment layout -> destinations ------------------------
    const int rbase = bm + m0 + (lane >> 2);
    const int cbase = bn + n0 + 2 * (lane & 3);
    #pragma unroll
    for (int mi = 0; mi < 4; mi++) {
        #pragma unroll
        for (int dr = 0; dr < 2; dr++) {
            const int row = rbase + mi * 16 + dr * 8;
            const int bidx = row >> 11;
            const int n = row & (kN - 1);
            #pragma unroll
            for (int ni = 0; ni < 4; ni++) {
                const int col = cbase + ni * 8;
                float2 v;
                v.x = acc[mi][ni][dr * 2 + 0];
                v.y = acc[mi][ni][dr * 2 + 1];
                if (MODE == 0) {
                    if (col < kH * kD) {
                        const int h = col >> 6, d = col & 63;
                        v.x *= kScale; v.y *= kScale;
                        *reinterpret_cast<float2*>(
                            g_q + (((size_t)(bidx * kH + h)) * kN + n) * kD + d) = v;
                    } else {
                        const int c = col - kH * kD;
                        const int h = c >> 6, d = c & 63;
                        *reinterpret_cast<float2*>(
                            g_k + (((size_t)(bidx * kH + h)) * kN + n) * kD + d) = v;
                    }
                } else if (MODE == 1) {
                    const int h = col >> 6, d = col & 63;
                    *reinterpret_cast<float2*>(
                        g_v + (((size_t)(bidx * kH + h)) * kN + n) * kD + d) = v;
                } else {
                    v.x += bias[col];
                    v.y += bias[col + 1];
                    *reinterpret_cast<float2*>(outp + (size_t)row * kDim + col) = v;
                }
            }
        }
    }
}

// ---------------------------------------------------------------------------
// Attention: 1 query/thread, online softmax, K/V tiles in shared (fp32 FFMA).
// Output tf32-rounded (feeds the out-proj tf32 GEMM).
// ---------------------------------------------------------------------------
__global__ __launch_bounds__(128) void attn_kernel() {
    const int bh = blockIdx.y;
    const int row = blockIdx.x * 128 + threadIdx.x;
    const float* __restrict__ Qp = g_q + (size_t)bh * kN * kD;
    const float* __restrict__ Kp = g_k + (size_t)bh * kN * kD;
    const float* __restrict__ Vp = g_v + (size_t)bh * kN * kD;

    __shared__ float Ks[64][64];
    __shared__ float Vs[64][64];

    float q[64], o[64];
    #pragma unroll
    for (int e4 = 0; e4 < 16; e4++) {
        const float4 qa = reinterpret_cast<const float4*>(Qp + (size_t)row * kD)[e4];
        q[e4 * 4 + 0] = qa.x; q[e4 * 4 + 1] = qa.y;
        q[e4 * 4 + 2] = qa.z; q[e4 * 4 + 3] = qa.w;
    }
    #pragma unroll
    for (int e = 0; e < 64; e++) o[e] = 0.f;
    float m = -CUDART_INF_F;
    float l = 0.f;

    for (int kt = 0; kt < kN; kt += 64) {
        __syncthreads();
        const float4* ksrc = reinterpret_cast<const float4*>(Kp + (size_t)kt * kD);
        const float4* vsrc = reinterpret_cast<const float4*>(Vp + (size_t)kt * kD);
        float4* kdst = reinterpret_cast<float4*>(&Ks[0][0]);
        float4* vdst = reinterpret_cast<float4*>(&Vs[0][0]);
        #pragma unroll
        for (int i = 0; i < 8; i++) {
            kdst[threadIdx.x + i * 128] = ksrc[threadIdx.x + i * 128];
            vdst[threadIdx.x + i * 128] = vsrc[threadIdx.x + i * 128];
        }
        __syncthreads();

        for (int j = 0; j < 64; j++) {
            const float4* kr = reinterpret_cast<const float4*>(&Ks[j][0]);
            float s = 0.f;
            #pragma unroll
            for (int e4 = 0; e4 < 16; e4++) {
                const float4 kv = kr[e4];
                s = fmaf(q[e4 * 4 + 0], kv.x, s);
                s = fmaf(q[e4 * 4 + 1], kv.y, s);
                s = fmaf(q[e4 * 4 + 2], kv.z, s);
                s = fmaf(q[e4 * 4 + 3], kv.w, s);
            }
            if (s > m) {
                const float corr = __expf(m - s);
                m = s;
                l *= corr;
                #pragma unroll
                for (int e = 0; e < 64; e++) o[e] *= corr;
            }
            const float p = __expf(s - m);
            l += p;
            const float4* vr = reinterpret_cast<const float4*>(&Vs[j][0]);
            #pragma unroll
            for (int e4 = 0; e4 < 16; e4++) {
                const float4 vv = vr[e4];
                o[e4 * 4 + 0] = fmaf(p, vv.x, o[e4 * 4 + 0]);
                o[e4 * 4 + 1] = fmaf(p, vv.y, o[e4 * 4 + 1]);
                o[e4 * 4 + 2] = fmaf(p, vv.z, o[e4 * 4 + 2]);
                o[e4 * 4 + 3] = fmaf(p, vv.w, o[e4 * 4 + 3]);
            }
        }
    }

    const float invl = 1.0f / l;
    const int b = bh >> 4;
    const int h = bh & 15;
    float* dst = g_attn + ((size_t)(b * kN + row)) * kDim + h * kD;
    #pragma unroll
    for (int e4 = 0; e4 < 16; e4++) {
        float4 ov;
        ov.x = to_tf32(o[e4 * 4 + 0] * invl);
        ov.y = to_tf32(o[e4 * 4 + 1] * invl);
        ov.z = to_tf32(o[e4 * 4 + 2] * invl);
        ov.w = to_tf32(o[e4 * 4 + 3] * invl);
        reinterpret_cast<float4*>(dst)[e4] = ov;
    }
}

// ---------------------------------------------------------------------------
extern "C" void kernel_launch(void* const* d_in, const int* in_sizes, int n_in,
                              void* d_out, int out_size) {
    const float* x     = (const float*)d_in[0];
    const float* gamma = (const float*)d_in[1];
    const float* beta  = (const float*)d_in[2];
    const float* W_qk  = (const float*)d_in[3];
    const float* W_v   = (const float*)d_in[4];
    const float* W_out = (const float*)d_in[5];
    const float* b_out = (const float*)d_in[6];
    float* out = (float*)d_out;

    cudaFuncSetAttribute(gemm_mma<0>, cudaFuncAttributeMaxDynamicSharedMemorySize, kGemmSmemBytes);
    cudaFuncSetAttribute(gemm_mma<1>, cudaFuncAttributeMaxDynamicSharedMemorySize, kGemmSmemBytes);
    cudaFuncSetAttribute(gemm_mma<2>, cudaFuncAttributeMaxDynamicSharedMemorySize, kGemmSmemBytes);

    float* wqk_t;  cudaGetSymbolAddress((void**)&wqk_t, g_wqk_t);
    float* wv_t;   cudaGetSymbolAddress((void**)&wv_t, g_wv_t);
    float* wout_t; cudaGetSymbolAddress((void**)&wout_t, g_wout_t);

    ln_kernel<<<kTokens, 256>>>(x, gamma, beta);
    transpose_tf32<<<dim3(kQKCols / 32, kDim / 32), dim3(32, 8)>>>(W_qk, wqk_t, kDim, kQKCols);
    transpose_tf32<<<dim3(kDim / 32, kDim / 32), dim3(32, 8)>>>(W_v, wv_t, kDim, kDim);
    transpose_tf32<<<dim3(kDim / 32, kDim / 32), dim3(32, 8)>>>(W_out, wout_t, kDim, kDim);

    gemm_mma<0><<<dim3(kQKCols / 128, kTokens / 128), 256, kGemmSmemBytes>>>(wqk_t, nullptr, nullptr);
    gemm_mma<1><<<dim3(kDim / 128, kTokens / 128), 256, kGemmSmemBytes>>>(wv_t, nullptr, nullptr);
    attn_kernel<<<dim3(kN / 128, kB * kH), 128>>>();
    gemm_mma<2><<<dim3(kDim / 128, kTokens / 128), 256, kGemmSmemBytes>>>(wout_t, out, b_out);
}

// round 4
// speedup vs baseline: 3.3841x; 2.5497x over previous
#include <cuda_runtime.h>
#include <math_constants.h>
#include <cstdint>

namespace {
constexpr int kB = 2;
constexpr int kN = 2048;
constexpr int kDim = 1024;
constexpr int kH = 16;
constexpr int kD = 64;
constexpr int kTokens = kB * kN;          // 4096
constexpr float kScale = 0.125f;          // 1/sqrt(64)
constexpr int kQKCols = 2 * kH * kD;      // 2048

constexpr int kPad = 36;                  // gemm smem row stride (floats)
constexpr int kStageFloats = 128 * kPad;
constexpr int kGemmSmemBytes = 2 * 2 * kStageFloats * 4;   // 73728

// attention smem: K stride 68, V stride 72 (bank-conflict-free frag loads)
constexpr int kKStride = 68;
constexpr int kVStride = 72;
constexpr int kAttnStageFloats = 64 * kKStride + 64 * kVStride;  // 8960
constexpr int kAttnSmemBytes = 2 * kAttnStageFloats * 4;         // 71680
}

// Scratch (device globals — no allocations allowed)
__device__ __align__(256) float g_xn[kTokens * kDim];
__device__ __align__(256) float g_q[kB * kH * kN * kD];      // (b,h,n,d), scaled, tf32
__device__ __align__(256) float g_k[kB * kH * kN * kD];      // tf32
__device__ __align__(256) float g_v[kB * kH * kN * kD];      // tf32
__device__ __align__(256) float g_attn[kTokens * kDim];      // tf32
__device__ __align__(256) float g_wqk_t[kQKCols * kDim];
__device__ __align__(256) float g_wv_t[kDim * kDim];
__device__ __align__(256) float g_wout_t[kDim * kDim];

// ---------------------------------------------------------------------------
// helpers
// ---------------------------------------------------------------------------
__device__ __forceinline__ float to_tf32(float x) {
    uint32_t u;
    asm("cvt.rna.tf32.f32 %0, %1;" : "=r"(u) : "f"(x));
    return __uint_as_float(u);
}

__device__ __forceinline__ uint32_t smem_u32(const void* p) {
    uint32_t a;
    asm("{ .reg .u64 t; cvta.to.shared.u64 t, %1; cvt.u32.u64 %0, t; }"
        : "=r"(a) : "l"(p));
    return a;
}

__device__ __forceinline__ void cp_async16(uint32_t dst, const void* src) {
    asm volatile("cp.async.cg.shared.global [%0], [%1], 16;" :: "r"(dst), "l"(src));
}
__device__ __forceinline__ void cp_commit() {
    asm volatile("cp.async.commit_group;");
}
template <int N> __device__ __forceinline__ void cp_wait() {
    asm volatile("cp.async.wait_group %0;" :: "n"(N));
}

// m16n8k8 tf32 mma: D += A@B, A row-major 16x8, B col-major 8x8, fp32 accum.
__device__ __forceinline__ void mma_tf32(float* c, const uint32_t* a, const uint32_t* b) {
    asm volatile(
        "mma.sync.aligned.m16n8k8.row.col.f32.tf32.tf32.f32 "
        "{%0,%1,%2,%3}, {%4,%5,%6,%7}, {%8,%9}, {%0,%1,%2,%3};"
        : "+f"(c[0]), "+f"(c[1]), "+f"(c[2]), "+f"(c[3])
        : "r"(a[0]), "r"(a[1]), "r"(a[2]), "r"(a[3]), "r"(b[0]), "r"(b[1]));
}

// ---------------------------------------------------------------------------
// LayerNorm
// ---------------------------------------------------------------------------
__global__ __launch_bounds__(256) void ln_kernel(const float* __restrict__ x,
                                                 const float* __restrict__ gamma,
                                                 const float* __restrict__ beta) {
    const int t = blockIdx.x;
    const int tid = threadIdx.x;
    const float4 xv = reinterpret_cast<const float4*>(x + (size_t)t * kDim)[tid];
    float s  = xv.x + xv.y + xv.z + xv.w;
    float ss = xv.x * xv.x + xv.y * xv.y + xv.z * xv.z + xv.w * xv.w;
    #pragma unroll
    for (int o = 16; o > 0; o >>= 1) {
        s  += __shfl_xor_sync(0xffffffffu, s, o);
        ss += __shfl_xor_sync(0xffffffffu, ss, o);
    }
    __shared__ float red_s[8], red_ss[8];
    if ((tid & 31) == 0) { red_s[tid >> 5] = s; red_ss[tid >> 5] = ss; }
    __syncthreads();
    float S = 0.f, SS = 0.f;
    #pragma unroll
    for (int i = 0; i < 8; i++) { S += red_s[i]; SS += red_ss[i]; }
    const float mu  = S * (1.0f / kDim);
    const float var = SS * (1.0f / kDim) - mu * mu;
    const float inv = rsqrtf(var + 1e-5f);
    const float4 g = reinterpret_cast<const float4*>(gamma)[tid];
    const float4 b = reinterpret_cast<const float4*>(beta)[tid];
    float4 out;
    out.x = to_tf32((xv.x - mu) * inv * g.x + b.x);
    out.y = to_tf32((xv.y - mu) * inv * g.y + b.y);
    out.z = to_tf32((xv.z - mu) * inv * g.z + b.z);
    out.w = to_tf32((xv.w - mu) * inv * g.w + b.w);
    reinterpret_cast<float4*>(g_xn + (size_t)t * kDim)[tid] = out;
}

// ---------------------------------------------------------------------------
// Transpose + tf32-round: src[rows][cols] -> dst[cols][rows]
// ---------------------------------------------------------------------------
__global__ __launch_bounds__(256) void transpose_tf32(const float* __restrict__ src,
                                                      float* __restrict__ dst,
                                                      int rows, int cols) {
    __shared__ float tile[32][33];
    const int bx = blockIdx.x * 32;
    const int by = blockIdx.y * 32;
    const int tx = threadIdx.x;
    #pragma unroll
    for (int i = threadIdx.y; i < 32; i += 8)
        tile[i][tx] = src[(size_t)(by + i) * cols + bx + tx];
    __syncthreads();
    #pragma unroll
    for (int i = threadIdx.y; i < 32; i += 8)
        dst[(size_t)(bx + i) * rows + by + tx] = to_tf32(tile[tx][i]);
}

// ---------------------------------------------------------------------------
// tf32 warp-MMA GEMM (unchanged from R3 except tf32-rounded q/k/v epilogue)
// ---------------------------------------------------------------------------
template <int MODE>
__global__ __launch_bounds__(256)
void gemm_mma(const float* __restrict__ Bt, float* __restrict__ outp,
              const float* __restrict__ bias) {
    extern __shared__ float smem_f[];
    const float* __restrict__ A = (MODE == 2) ? g_attn : g_xn;
    const int bm = blockIdx.y * 128;
    const int bn = blockIdx.x * 128;
    const int tid = threadIdx.x;
    const int wid = tid >> 5;
    const int lane = tid & 31;
    const int m0 = (wid & 1) * 64;
    const int n0 = (wid >> 1) * 32;

    float* sA[2] = {smem_f, smem_f + kStageFloats};
    float* sB[2] = {smem_f + 2 * kStageFloats, smem_f + 3 * kStageFloats};
    const uint32_t sAu[2] = {smem_u32(sA[0]), smem_u32(sA[1])};
    const uint32_t sBu[2] = {smem_u32(sB[0]), smem_u32(sB[1])};

    float acc[4][4][4];
    #pragma unroll
    for (int mi = 0; mi < 4; mi++)
        #pragma unroll
        for (int ni = 0; ni < 4; ni++)
            #pragma unroll
            for (int r = 0; r < 4; r++) acc[mi][ni][r] = 0.f;

    auto load_stage = [&](int t, int s) {
        const int k0 = t * 32;
        #pragma unroll
        for (int i = 0; i < 4; ++i) {
            const int idx = tid + i * 256;
            const int r = idx >> 3;
            const int c4 = (idx & 7) << 2;
            cp_async16(sAu[s] + (uint32_t)(r * kPad + c4) * 4,
                       A + (size_t)(bm + r) * kDim + k0 + c4);
        }
        #pragma unroll
        for (int i = 0; i < 4; ++i) {
            const int idx = tid + i * 256;
            const int r = idx >> 3;
            const int c4 = (idx & 7) << 2;
            cp_async16(sBu[s] + (uint32_t)(r * kPad + c4) * 4,
                       Bt + (size_t)(bn + r) * kDim + k0 + c4);
        }
        cp_commit();
    };

    load_stage(0, 0);

    for (int t = 0; t < 32; ++t) {
        const int s = t & 1;
        if (t + 1 < 32) { load_stage(t + 1, s ^ 1); cp_wait<1>(); }
        else            { cp_wait<0>(); }
        __syncthreads();

        const float* As = sA[s];
        const float* Bs = sB[s];
        #pragma unroll
        for (int ks = 0; ks < 4; ++ks) {
            const int kc = ks * 8 + (lane & 3);
            uint32_t a[4][4], b[4][2];
            #pragma unroll
            for (int mi = 0; mi < 4; mi++) {
                const int r = m0 + mi * 16 + (lane >> 2);
                a[mi][0] = __float_as_uint(As[r * kPad + kc]);
                a[mi][1] = __float_as_uint(As[(r + 8) * kPad + kc]);
                a[mi][2] = __float_as_uint(As[r * kPad + kc + 4]);
                a[mi][3] = __float_as_uint(As[(r + 8) * kPad + kc + 4]);
            }
            #pragma unroll
            for (int ni = 0; ni < 4; ni++) {
                const int n = n0 + ni * 8 + (lane >> 2);
                b[ni][0] = __float_as_uint(Bs[n * kPad + kc]);
                b[ni][1] = __float_as_uint(Bs[n * kPad + kc + 4]);
            }
            #pragma unroll
            for (int mi = 0; mi < 4; mi++)
                #pragma unroll
                for (int ni = 0; ni < 4; ni++)
                    mma_tf32(acc[mi][ni], a[mi], b[ni]);
        }
        __syncthreads();
    }

    const int rbase = bm + m0 + (lane >> 2);
    const int cbase = bn + n0 + 2 * (lane & 3);
    #pragma unroll
    for (int mi = 0; mi < 4; mi++) {
        #pragma unroll
        for (int dr = 0; dr < 2; dr++) {
            const int row = rbase + mi * 16 + dr * 8;
            const int bidx = row >> 11;
            const int n = row & (kN - 1);
            #pragma unroll
            for (int ni = 0; ni < 4; ni++) {
                const int col = cbase + ni * 8;
                float2 v;
                v.x = acc[mi][ni][dr * 2 + 0];
                v.y = acc[mi][ni][dr * 2 + 1];
                if (MODE == 0) {
                    if (col < kH * kD) {
                        const int h = col >> 6, d = col & 63;
                        v.x = to_tf32(v.x * kScale);
                        v.y = to_tf32(v.y * kScale);
                        *reinterpret_cast<float2*>(
                            g_q + (((size_t)(bidx * kH + h)) * kN + n) * kD + d) = v;
                    } else {
                        const int c = col - kH * kD;
                        const int h = c >> 6, d = c & 63;
                        v.x = to_tf32(v.x);
                        v.y = to_tf32(v.y);
                        *reinterpret_cast<float2*>(
                            g_k + (((size_t)(bidx * kH + h)) * kN + n) * kD + d) = v;
                    }
                } else if (MODE == 1) {
                    const int h = col >> 6, d = col & 63;
                    v.x = to_tf32(v.x);
                    v.y = to_tf32(v.y);
                    *reinterpret_cast<float2*>(
                        g_v + (((size_t)(bidx * kH + h)) * kN + n) * kD + d) = v;
                } else {
                    v.x += bias[col];
                    v.y += bias[col + 1];
                    *reinterpret_cast<float2*>(outp + (size_t)row * kDim + col) = v;
                }
            }
        }
    }
}

// ---------------------------------------------------------------------------
// Flash attention on mma.sync tf32.
// CTA = 128 queries x 1 head; 8 warps x 16 rows. kv-tile = 64 keys,
// double-buffered cp.async. Q frags register-resident; online softmax in
// C-fragment registers; P reshuffled C->A layout via shfl.
// ---------------------------------------------------------------------------
__global__ __launch_bounds__(256) void attn_mma_kernel() {
    extern __shared__ float smem_f[];
    const int bh = blockIdx.y;
    const int tid = threadIdx.x;
    const int wid = tid >> 5;
    const int lane = tid & 31;
    const int r = lane >> 2;      // group id (row within m16 half)
    const int g = lane & 3;       // thread in group
    const int qrow0 = blockIdx.x * 128 + wid * 16;

    const float* __restrict__ Qp = g_q + (size_t)bh * kN * kD;
    const float* __restrict__ Kp = g_k + (size_t)bh * kN * kD;
    const float* __restrict__ Vp = g_v + (size_t)bh * kN * kD;

    float* Ksm[2] = {smem_f, smem_f + kAttnStageFloats};
    float* Vsm[2] = {smem_f + 64 * kKStride, smem_f + kAttnStageFloats + 64 * kKStride};
    const uint32_t Ku[2] = {smem_u32(Ksm[0]), smem_u32(Ksm[1])};
    const uint32_t Vu[2] = {smem_u32(Vsm[0]), smem_u32(Vsm[1])};

    // Q fragments (row-major A): 8 k-tiles x 4 regs, live whole kernel.
    uint32_t qf[8][4];
    #pragma unroll
    for (int kt = 0; kt < 8; ++kt) {
        const float* q0 = Qp + (size_t)(qrow0 + r) * kD + kt * 8 + g;
        const float* q1 = Qp + (size_t)(qrow0 + r + 8) * kD + kt * 8 + g;
        qf[kt][0] = __float_as_uint(q0[0]);
        qf[kt][1] = __float_as_uint(q1[0]);
        qf[kt][2] = __float_as_uint(q0[4]);
        qf[kt][3] = __float_as_uint(q1[4]);
    }

    float o[8][4];
    #pragma unroll
    for (int i = 0; i < 8; i++)
        #pragma unroll
        for (int j = 0; j < 4; j++) o[i][j] = 0.f;
    float m0 = -CUDART_INF_F, m1 = -CUDART_INF_F;
    float l0 = 0.f, l1 = 0.f;

    auto load_stage = [&](int t, int s) {
        const float* ksrc = Kp + (size_t)t * 64 * kD;
        const float* vsrc = Vp + (size_t)t * 64 * kD;
        #pragma unroll
        for (int i = 0; i < 4; ++i) {
            const int idx = tid + i * 256;           // 0..1023
            const int rr = idx >> 4;                 // 0..63
            const int c4 = (idx & 15) << 2;          // 0..60
            cp_async16(Ku[s] + (uint32_t)(rr * kKStride + c4) * 4, ksrc + rr * kD + c4);
            cp_async16(Vu[s] + (uint32_t)(rr * kVStride + c4) * 4, vsrc + rr * kD + c4);
        }
        cp_commit();
    };

    load_stage(0, 0);

    for (int t = 0; t < 32; ++t) {
        const int s = t & 1;
        if (t + 1 < 32) { load_stage(t + 1, s ^ 1); cp_wait<1>(); }
        else            { cp_wait<0>(); }
        __syncthreads();

        const float* K_ = Ksm[s];
        const float* V_ = Vsm[s];

        // ---- S = Q @ K^T  (m16 x n64 per warp) ----------------------------
        float sf[8][4];
        #pragma unroll
        for (int nt = 0; nt < 8; ++nt) {
            sf[nt][0] = sf[nt][1] = sf[nt][2] = sf[nt][3] = 0.f;
            const float* kb = K_ + (nt * 8 + r) * kKStride;
            #pragma unroll
            for (int kt = 0; kt < 8; ++kt) {
                uint32_t b[2];
                b[0] = __float_as_uint(kb[kt * 8 + g]);
                b[1] = __float_as_uint(kb[kt * 8 + g + 4]);
                mma_tf32(sf[nt], qf[kt], b);
            }
        }

        // ---- online softmax ------------------------------------------------
        float mx0 = -CUDART_INF_F, mx1 = -CUDART_INF_F;
        #pragma unroll
        for (int nt = 0; nt < 8; ++nt) {
            mx0 = fmaxf(mx0, fmaxf(sf[nt][0], sf[nt][1]));
            mx1 = fmaxf(mx1, fmaxf(sf[nt][2], sf[nt][3]));
        }
        mx0 = fmaxf(mx0, __shfl_xor_sync(0xffffffffu, mx0, 1));
        mx0 = fmaxf(mx0, __shfl_xor_sync(0xffffffffu, mx0, 2));
        mx1 = fmaxf(mx1, __shfl_xor_sync(0xffffffffu, mx1, 1));
        mx1 = fmaxf(mx1, __shfl_xor_sync(0xffffffffu, mx1, 2));
        const float mn0 = fmaxf(m0, mx0);
        const float mn1 = fmaxf(m1, mx1);
        const float c0 = __expf(m0 - mn0);
        const float c1 = __expf(m1 - mn1);
        m0 = mn0; m1 = mn1;
        #pragma unroll
        for (int nt = 0; nt < 8; ++nt) {
            o[nt][0] *= c0; o[nt][1] *= c0;
            o[nt][2] *= c1; o[nt][3] *= c1;
        }
        float sum0 = 0.f, sum1 = 0.f;
        #pragma unroll
        for (int nt = 0; nt < 8; ++nt) {
            sf[nt][0] = to_tf32(__expf(sf[nt][0] - mn0));
            sf[nt][1] = to_tf32(__expf(sf[nt][1] - mn0));
            sf[nt][2] = to_tf32(__expf(sf[nt][2] - mn1));
            sf[nt][3] = to_tf32(__expf(sf[nt][3] - mn1));
            sum0 += sf[nt][0] + sf[nt][1];
            sum1 += sf[nt][2] + sf[nt][3];
        }
        sum0 += __shfl_xor_sync(0xffffffffu, sum0, 1);
        sum0 += __shfl_xor_sync(0xffffffffu, sum0, 2);
        sum1 += __shfl_xor_sync(0xffffffffu, sum1, 1);
        sum1 += __shfl_xor_sync(0xffffffffu, sum1, 2);
        l0 = l0 * c0 + sum0;
        l1 = l1 * c1 + sum1;

        // ---- O += P @ V  (reshuffle P: C-frag -> A-frag layout) ------------
        const int srcA = (lane & ~3) | (g >> 1);
        const int srcB = srcA + 2;
        const bool odd = g & 1;
        #pragma unroll
        for (int kt = 0; kt < 8; ++kt) {
            const float x00 = __shfl_sync(0xffffffffu, sf[kt][0], srcA);
            const float x01 = __shfl_sync(0xffffffffu, sf[kt][1], srcA);
            const float x10 = __shfl_sync(0xffffffffu, sf[kt][2], srcA);
            const float x11 = __shfl_sync(0xffffffffu, sf[kt][3], srcA);
            const float y00 = __shfl_sync(0xffffffffu, sf[kt][0], srcB);
            const float y01 = __shfl_sync(0xffffffffu, sf[kt][1], srcB);
            const float y10 = __shfl_sync(0xffffffffu, sf[kt][2], srcB);
            const float y11 = __shfl_sync(0xffffffffu, sf[kt][3], srcB);
            uint32_t a[4];
            a[0] = __float_as_uint(odd ? x01 : x00);
            a[1] = __float_as_uint(odd ? x11 : x10);
            a[2] = __float_as_uint(odd ? y01 : y00);
            a[3] = __float_as_uint(odd ? y11 : y10);
            const float* vb0 = V_ + (kt * 8 + g) * kVStride + r;
            const float* vb1 = V_ + (kt * 8 + g + 4) * kVStride + r;
            #pragma unroll
            for (int nt2 = 0; nt2 < 8; ++nt2) {
                uint32_t b[2];
                b[0] = __float_as_uint(vb0[nt2 * 8]);
                b[1] = __float_as_uint(vb1[nt2 * 8]);
                mma_tf32(o[nt2], a, b);
            }
        }
        __syncthreads();
    }

    // ---- epilogue ----------------------------------------------------------
    const float invl0 = 1.0f / l0;
    const float invl1 = 1.0f / l1;
    const int b = bh >> 4;
    const int h = bh & 15;
    const int row0 = qrow0 + r;
    const int row1 = qrow0 + r + 8;
    float* d0 = g_attn + ((size_t)(b * kN + row0)) * kDim + h * kD;
    float* d1 = g_attn + ((size_t)(b * kN + row1)) * kDim + h * kD;
    #pragma unroll
    for (int nt2 = 0; nt2 < 8; ++nt2) {
        const int col = nt2 * 8 + 2 * g;
        float2 v0, v1;
        v0.x = to_tf32(o[nt2][0] * invl0);
        v0.y = to_tf32(o[nt2][1] * invl0);
        v1.x = to_tf32(o[nt2][2] * invl1);
        v1.y = to_tf32(o[nt2][3] * invl1);
        *reinterpret_cast<float2*>(d0 + col) = v0;
        *reinterpret_cast<float2*>(d1 + col) = v1;
    }
}

// ---------------------------------------------------------------------------
extern "C" void kernel_launch(void* const* d_in, const int* in_sizes, int n_in,
                              void* d_out, int out_size) {
    const float* x     = (const float*)d_in[0];
    const float* gamma = (const float*)d_in[1];
    const float* beta  = (const float*)d_in[2];
    const float* W_qk  = (const float*)d_in[3];
    const float* W_v   = (const float*)d_in[4];
    const float* W_out = (const float*)d_in[5];
    const float* b_out = (const float*)d_in[6];
    float* out = (float*)d_out;

    cudaFuncSetAttribute(gemm_mma<0>, cudaFuncAttributeMaxDynamicSharedMemorySize, kGemmSmemBytes);
    cudaFuncSetAttribute(gemm_mma<1>, cudaFuncAttributeMaxDynamicSharedMemorySize, kGemmSmemBytes);
    cudaFuncSetAttribute(gemm_mma<2>, cudaFuncAttributeMaxDynamicSharedMemorySize, kGemmSmemBytes);
    cudaFuncSetAttribute(attn_mma_kernel, cudaFuncAttributeMaxDynamicSharedMemorySize, kAttnSmemBytes);

    float* wqk_t;  cudaGetSymbolAddress((void**)&wqk_t, g_wqk_t);
    float* wv_t;   cudaGetSymbolAddress((void**)&wv_t, g_wv_t);
    float* wout_t; cudaGetSymbolAddress((void**)&wout_t, g_wout_t);

    ln_kernel<<<kTokens, 256>>>(x, gamma, beta);
    transpose_tf32<<<dim3(kQKCols / 32, kDim / 32), dim3(32, 8)>>>(W_qk, wqk_t, kDim, kQKCols);
    transpose_tf32<<<dim3(kDim / 32, kDim / 32), dim3(32, 8)>>>(W_v, wv_t, kDim, kDim);
    transpose_tf32<<<dim3(kDim / 32, kDim / 32), dim3(32, 8)>>>(W_out, wout_t, kDim, kDim);

    gemm_mma<0><<<dim3(kQKCols / 128, kTokens / 128), 256, kGemmSmemBytes>>>(wqk_t, nullptr, nullptr);
    gemm_mma<1><<<dim3(kDim / 128, kTokens / 128), 256, kGemmSmemBytes>>>(wv_t, nullptr, nullptr);
    attn_mma_kernel<<<dim3(kN / 128, kB * kH), 256, kAttnSmemBytes>>>();
    gemm_mma<2><<<dim3(kDim / 128, kTokens / 128), 256, kGemmSmemBytes>>>(wout_t, out, b_out);
}

// round 5
// speedup vs baseline: 4.2627x; 1.2596x over previous
#include <cuda_runtime.h>
#include <math_constants.h>
#include <cstdint>

namespace {
constexpr int kB = 2;
constexpr int kN = 2048;
constexpr int kDim = 1024;
constexpr int kH = 16;
constexpr int kD = 64;
constexpr int kTokens = kB * kN;          // 4096
constexpr float kScale = 0.125f;          // 1/sqrt(64)
constexpr int kQKCols = 2 * kH * kD;      // 2048

constexpr int kPad = 36;                  // gemm smem row stride (floats)
constexpr int kStageFloats = 128 * kPad;
constexpr int kGemmSmemBytes = 2 * 2 * kStageFloats * 4;   // 73728

// attention smem: K stride 68, V stride 72 (bank-conflict-free frag loads)
constexpr int kKStride = 68;
constexpr int kVStride = 72;
constexpr int kAttnStageFloats = 64 * kKStride + 64 * kVStride;  // 8960
constexpr int kAttnSmemBytes = 2 * kAttnStageFloats * 4;         // 71680
}

// Scratch (device globals — no allocations allowed)
__device__ __align__(256) float g_xn[kTokens * kDim];
__device__ __align__(256) float g_q[kB * kH * kN * kD];      // (b,h,n,d), scaled, tf32
__device__ __align__(256) float g_k[kB * kH * kN * kD];      // tf32
__device__ __align__(256) float g_v[kB * kH * kN * kD];      // tf32
__device__ __align__(256) float g_attn[kTokens * kDim];      // tf32
__device__ __align__(256) float g_wqk_t[kQKCols * kDim];
__device__ __align__(256) float g_wv_t[kDim * kDim];
__device__ __align__(256) float g_wout_t[kDim * kDim];

// ---------------------------------------------------------------------------
// helpers
// ---------------------------------------------------------------------------
__device__ __forceinline__ float to_tf32(float x) {
    uint32_t u;
    asm("cvt.rna.tf32.f32 %0, %1;" : "=r"(u) : "f"(x));
    return __uint_as_float(u);
}

__device__ __forceinline__ uint32_t smem_u32(const void* p) {
    uint32_t a;
    asm("{ .reg .u64 t; cvta.to.shared.u64 t, %1; cvt.u32.u64 %0, t; }"
        : "=r"(a) : "l"(p));
    return a;
}

__device__ __forceinline__ void cp_async16(uint32_t dst, const void* src) {
    asm volatile("cp.async.cg.shared.global [%0], [%1], 16;" :: "r"(dst), "l"(src));
}
__device__ __forceinline__ void cp_commit() {
    asm volatile("cp.async.commit_group;");
}
template <int N> __device__ __forceinline__ void cp_wait() {
    asm volatile("cp.async.wait_group %0;" :: "n"(N));
}

// m16n8k8 tf32 mma: D += A@B, A row-major 16x8, B col-major 8x8, fp32 accum.
__device__ __forceinline__ void mma_tf32(float* c, const uint32_t* a, const uint32_t* b) {
    asm volatile(
        "mma.sync.aligned.m16n8k8.row.col.f32.tf32.tf32.f32 "
        "{%0,%1,%2,%3}, {%4,%5,%6,%7}, {%8,%9}, {%0,%1,%2,%3};"
        : "+f"(c[0]), "+f"(c[1]), "+f"(c[2]), "+f"(c[3])
        : "r"(a[0]), "r"(a[1]), "r"(a[2]), "r"(a[3]), "r"(b[0]), "r"(b[1]));
}

// ---------------------------------------------------------------------------
// LayerNorm
// ---------------------------------------------------------------------------
__global__ __launch_bounds__(256) void ln_kernel(const float* __restrict__ x,
                                                 const float* __restrict__ gamma,
                                                 const float* __restrict__ beta) {
    const int t = blockIdx.x;
    const int tid = threadIdx.x;
    const float4 xv = reinterpret_cast<const float4*>(x + (size_t)t * kDim)[tid];
    float s  = xv.x + xv.y + xv.z + xv.w;
    float ss = xv.x * xv.x + xv.y * xv.y + xv.z * xv.z + xv.w * xv.w;
    #pragma unroll
    for (int o = 16; o > 0; o >>= 1) {
        s  += __shfl_xor_sync(0xffffffffu, s, o);
        ss += __shfl_xor_sync(0xffffffffu, ss, o);
    }
    __shared__ float red_s[8], red_ss[8];
    if ((tid & 31) == 0) { red_s[tid >> 5] = s; red_ss[tid >> 5] = ss; }
    __syncthreads();
    float S = 0.f, SS = 0.f;
    #pragma unroll
    for (int i = 0; i < 8; i++) { S += red_s[i]; SS += red_ss[i]; }
    const float mu  = S * (1.0f / kDim);
    const float var = SS * (1.0f / kDim) - mu * mu;
    const float inv = rsqrtf(var + 1e-5f);
    const float4 g = reinterpret_cast<const float4*>(gamma)[tid];
    const float4 b = reinterpret_cast<const float4*>(beta)[tid];
    float4 out;
    out.x = to_tf32((xv.x - mu) * inv * g.x + b.x);
    out.y = to_tf32((xv.y - mu) * inv * g.y + b.y);
    out.z = to_tf32((xv.z - mu) * inv * g.z + b.z);
    out.w = to_tf32((xv.w - mu) * inv * g.w + b.w);
    reinterpret_cast<float4*>(g_xn + (size_t)t * kDim)[tid] = out;
}

// ---------------------------------------------------------------------------
// Transpose + tf32-round: src[rows][cols] -> dst[cols][rows]
// ---------------------------------------------------------------------------
__global__ __launch_bounds__(256) void transpose_tf32(const float* __restrict__ src,
                                                      float* __restrict__ dst,
                                                      int rows, int cols) {
    __shared__ float tile[32][33];
    const int bx = blockIdx.x * 32;
    const int by = blockIdx.y * 32;
    const int tx = threadIdx.x;
    #pragma unroll
    for (int i = threadIdx.y; i < 32; i += 8)
        tile[i][tx] = src[(size_t)(by + i) * cols + bx + tx];
    __syncthreads();
    #pragma unroll
    for (int i = threadIdx.y; i < 32; i += 8)
        dst[(size_t)(bx + i) * rows + by + tx] = to_tf32(tile[tx][i]);
}

// ---------------------------------------------------------------------------
// tf32 warp-MMA GEMM: 128x128 CTA tile, 4 warps (2x2) of 64x64 each.
// K-tile 32, double-buffered cp.async, pad-36 smem (conflict-free).
// ---------------------------------------------------------------------------
template <int MODE>
__global__ __launch_bounds__(128)
void gemm_mma(const float* __restrict__ Bt, float* __restrict__ outp,
              const float* __restrict__ bias) {
    extern __shared__ float smem_f[];
    const float* __restrict__ A = (MODE == 2) ? g_attn : g_xn;
    const int bm = blockIdx.y * 128;
    const int bn = blockIdx.x * 128;
    const int tid = threadIdx.x;
    const int wid = tid >> 5;
    const int lane = tid & 31;
    const int m0 = (wid & 1) * 64;
    const int n0 = (wid >> 1) * 64;

    float* sA[2] = {smem_f, smem_f + kStageFloats};
    float* sB[2] = {smem_f + 2 * kStageFloats, smem_f + 3 * kStageFloats};
    const uint32_t sAu[2] = {smem_u32(sA[0]), smem_u32(sA[1])};
    const uint32_t sBu[2] = {smem_u32(sB[0]), smem_u32(sB[1])};

    float acc[4][8][4];
    #pragma unroll
    for (int mi = 0; mi < 4; mi++)
        #pragma unroll
        for (int ni = 0; ni < 8; ni++)
            #pragma unroll
            for (int r = 0; r < 4; r++) acc[mi][ni][r] = 0.f;

    auto load_stage = [&](int t, int s) {
        const int k0 = t * 32;
        #pragma unroll
        for (int i = 0; i < 8; ++i) {
            const int idx = tid + i * 128;           // 0..1023
            const int r = idx >> 3;
            const int c4 = (idx & 7) << 2;
            cp_async16(sAu[s] + (uint32_t)(r * kPad + c4) * 4,
                       A + (size_t)(bm + r) * kDim + k0 + c4);
        }
        #pragma unroll
        for (int i = 0; i < 8; ++i) {
            const int idx = tid + i * 128;
            const int r = idx >> 3;
            const int c4 = (idx & 7) << 2;
            cp_async16(sBu[s] + (uint32_t)(r * kPad + c4) * 4,
                       Bt + (size_t)(bn + r) * kDim + k0 + c4);
        }
        cp_commit();
    };

    load_stage(0, 0);

    for (int t = 0; t < 32; ++t) {
        const int s = t & 1;
        if (t + 1 < 32) { load_stage(t + 1, s ^ 1); cp_wait<1>(); }
        else            { cp_wait<0>(); }
        __syncthreads();

        const float* As = sA[s];
        const float* Bs = sB[s];
        #pragma unroll
        for (int ks = 0; ks < 4; ++ks) {
            const int kc = ks * 8 + (lane & 3);
            uint32_t a[4][4], b[8][2];
            #pragma unroll
            for (int mi = 0; mi < 4; mi++) {
                const int r = m0 + mi * 16 + (lane >> 2);
                a[mi][0] = __float_as_uint(As[r * kPad + kc]);
                a[mi][1] = __float_as_uint(As[(r + 8) * kPad + kc]);
                a[mi][2] = __float_as_uint(As[r * kPad + kc + 4]);
                a[mi][3] = __float_as_uint(As[(r + 8) * kPad + kc + 4]);
            }
            #pragma unroll
            for (int ni = 0; ni < 8; ni++) {
                const int n = n0 + ni * 8 + (lane >> 2);
                b[ni][0] = __float_as_uint(Bs[n * kPad + kc]);
                b[ni][1] = __float_as_uint(Bs[n * kPad + kc + 4]);
            }
            #pragma unroll
            for (int mi = 0; mi < 4; mi++)
                #pragma unroll
                for (int ni = 0; ni < 8; ni++)
                    mma_tf32(acc[mi][ni], a[mi], b[ni]);
        }
        __syncthreads();
    }

    const int rbase = bm + m0 + (lane >> 2);
    const int cbase = bn + n0 + 2 * (lane & 3);
    #pragma unroll
    for (int mi = 0; mi < 4; mi++) {
        #pragma unroll
        for (int dr = 0; dr < 2; dr++) {
            const int row = rbase + mi * 16 + dr * 8;
            const int bidx = row >> 11;
            const int n = row & (kN - 1);
            #pragma unroll
            for (int ni = 0; ni < 8; ni++) {
                const int col = cbase + ni * 8;
                float2 v;
                v.x = acc[mi][ni][dr * 2 + 0];
                v.y = acc[mi][ni][dr * 2 + 1];
                if (MODE == 0) {
                    if (col < kH * kD) {
                        const int h = col >> 6, d = col & 63;
                        v.x = to_tf32(v.x * kScale);
                        v.y = to_tf32(v.y * kScale);
                        *reinterpret_cast<float2*>(
                            g_q + (((size_t)(bidx * kH + h)) * kN + n) * kD + d) = v;
                    } else {
                        const int c = col - kH * kD;
                        const int h = c >> 6, d = c & 63;
                        v.x = to_tf32(v.x);
                        v.y = to_tf32(v.y);
                        *reinterpret_cast<float2*>(
                            g_k + (((size_t)(bidx * kH + h)) * kN + n) * kD + d) = v;
                    }
                } else if (MODE == 1) {
                    const int h = col >> 6, d = col & 63;
                    v.x = to_tf32(v.x);
                    v.y = to_tf32(v.y);
                    *reinterpret_cast<float2*>(
                        g_v + (((size_t)(bidx * kH + h)) * kN + n) * kD + d) = v;
                } else {
                    v.x += bias[col];
                    v.y += bias[col + 1];
                    *reinterpret_cast<float2*>(outp + (size_t)row * kDim + col) = v;
                }
            }
        }
    }
}

// ---------------------------------------------------------------------------
// Flash attention on mma.sync tf32. CTA = 128 queries x 1 head; 4 warps of
// m32 x n64 (two m16 row blocks per warp share every K/V b-fragment).
// kv-tile = 64 keys, double-buffered cp.async.
// ---------------------------------------------------------------------------
__global__ __launch_bounds__(128) void attn_mma_kernel() {
    extern __shared__ float smem_f[];
    const int bh = blockIdx.y;
    const int tid = threadIdx.x;
    const int wid = tid >> 5;
    const int lane = tid & 31;
    const int r = lane >> 2;
    const int g = lane & 3;
    const int qrow0 = blockIdx.x * 128 + wid * 32;

    const float* __restrict__ Qp = g_q + (size_t)bh * kN * kD;
    const float* __restrict__ Kp = g_k + (size_t)bh * kN * kD;
    const float* __restrict__ Vp = g_v + (size_t)bh * kN * kD;

    float* Ksm[2] = {smem_f, smem_f + kAttnStageFloats};
    float* Vsm[2] = {smem_f + 64 * kKStride, smem_f + kAttnStageFloats + 64 * kKStride};
    const uint32_t Ku[2] = {smem_u32(Ksm[0]), smem_u32(Ksm[1])};
    const uint32_t Vu[2] = {smem_u32(Vsm[0]), smem_u32(Vsm[1])};

    // Q fragments for two m16 blocks (rows qrow0.. and qrow0+16..)
    uint32_t qfA[8][4], qfB[8][4];
    #pragma unroll
    for (int kt = 0; kt < 8; ++kt) {
        const float* qa0 = Qp + (size_t)(qrow0 + r) * kD + kt * 8 + g;
        const float* qa1 = Qp + (size_t)(qrow0 + r + 8) * kD + kt * 8 + g;
        const float* qb0 = Qp + (size_t)(qrow0 + r + 16) * kD + kt * 8 + g;
        const float* qb1 = Qp + (size_t)(qrow0 + r + 24) * kD + kt * 8 + g;
        qfA[kt][0] = __float_as_uint(qa0[0]);
        qfA[kt][1] = __float_as_uint(qa1[0]);
        qfA[kt][2] = __float_as_uint(qa0[4]);
        qfA[kt][3] = __float_as_uint(qa1[4]);
        qfB[kt][0] = __float_as_uint(qb0[0]);
        qfB[kt][1] = __float_as_uint(qb1[0]);
        qfB[kt][2] = __float_as_uint(qb0[4]);
        qfB[kt][3] = __float_as_uint(qb1[4]);
    }

    float oA[8][4], oB[8][4];
    #pragma unroll
    for (int i = 0; i < 8; i++)
        #pragma unroll
        for (int j = 0; j < 4; j++) { oA[i][j] = 0.f; oB[i][j] = 0.f; }
    float mA0 = -CUDART_INF_F, mA1 = -CUDART_INF_F;
    float mB0 = -CUDART_INF_F, mB1 = -CUDART_INF_F;
    float lA0 = 0.f, lA1 = 0.f, lB0 = 0.f, lB1 = 0.f;

    auto load_stage = [&](int t, int s) {
        const float* ksrc = Kp + (size_t)t * 64 * kD;
        const float* vsrc = Vp + (size_t)t * 64 * kD;
        #pragma unroll
        for (int i = 0; i < 8; ++i) {
            const int idx = tid + i * 128;           // 0..1023
            const int rr = idx >> 4;
            const int c4 = (idx & 15) << 2;
            cp_async16(Ku[s] + (uint32_t)(rr * kKStride + c4) * 4, ksrc + rr * kD + c4);
            cp_async16(Vu[s] + (uint32_t)(rr * kVStride + c4) * 4, vsrc + rr * kD + c4);
        }
        cp_commit();
    };

    load_stage(0, 0);

    const int srcA = (lane & ~3) | (g >> 1);
    const int srcB = srcA + 2;
    const bool odd = g & 1;

    for (int t = 0; t < 32; ++t) {
        const int s = t & 1;
        if (t + 1 < 32) { load_stage(t + 1, s ^ 1); cp_wait<1>(); }
        else            { cp_wait<0>(); }
        __syncthreads();

        const float* K_ = Ksm[s];
        const float* V_ = Vsm[s];

        // ---- S = Q @ K^T (m32 x n64, b-frags shared by both row blocks) ---
        float sfA[8][4], sfB[8][4];
        #pragma unroll
        for (int nt = 0; nt < 8; ++nt) {
            sfA[nt][0] = sfA[nt][1] = sfA[nt][2] = sfA[nt][3] = 0.f;
            sfB[nt][0] = sfB[nt][1] = sfB[nt][2] = sfB[nt][3] = 0.f;
            const float* kb = K_ + (nt * 8 + r) * kKStride;
            #pragma unroll
            for (int kt = 0; kt < 8; ++kt) {
                uint32_t b[2];
                b[0] = __float_as_uint(kb[kt * 8 + g]);
                b[1] = __float_as_uint(kb[kt * 8 + g + 4]);
                mma_tf32(sfA[nt], qfA[kt], b);
                mma_tf32(sfB[nt], qfB[kt], b);
            }
        }

        // ---- online softmax (4 row-stats) ----------------------------------
        float xA0 = -CUDART_INF_F, xA1 = -CUDART_INF_F;
        float xB0 = -CUDART_INF_F, xB1 = -CUDART_INF_F;
        #pragma unroll
        for (int nt = 0; nt < 8; ++nt) {
            xA0 = fmaxf(xA0, fmaxf(sfA[nt][0], sfA[nt][1]));
            xA1 = fmaxf(xA1, fmaxf(sfA[nt][2], sfA[nt][3]));
            xB0 = fmaxf(xB0, fmaxf(sfB[nt][0], sfB[nt][1]));
            xB1 = fmaxf(xB1, fmaxf(sfB[nt][2], sfB[nt][3]));
        }
        #pragma unroll
        for (int o2 = 1; o2 <= 2; o2 <<= 1) {
            xA0 = fmaxf(xA0, __shfl_xor_sync(0xffffffffu, xA0, o2));
            xA1 = fmaxf(xA1, __shfl_xor_sync(0xffffffffu, xA1, o2));
            xB0 = fmaxf(xB0, __shfl_xor_sync(0xffffffffu, xB0, o2));
            xB1 = fmaxf(xB1, __shfl_xor_sync(0xffffffffu, xB1, o2));
        }
        const float nA0 = fmaxf(mA0, xA0), nA1 = fmaxf(mA1, xA1);
        const float nB0 = fmaxf(mB0, xB0), nB1 = fmaxf(mB1, xB1);
        const float cA0 = __expf(mA0 - nA0), cA1 = __expf(mA1 - nA1);
        const float cB0 = __expf(mB0 - nB0), cB1 = __expf(mB1 - nB1);
        mA0 = nA0; mA1 = nA1; mB0 = nB0; mB1 = nB1;
        #pragma unroll
        for (int nt = 0; nt < 8; ++nt) {
            oA[nt][0] *= cA0; oA[nt][1] *= cA0;
            oA[nt][2] *= cA1; oA[nt][3] *= cA1;
            oB[nt][0] *= cB0; oB[nt][1] *= cB0;
            oB[nt][2] *= cB1; oB[nt][3] *= cB1;
        }
        float sA0 = 0.f, sA1 = 0.f, sB0 = 0.f, sB1 = 0.f;
        #pragma unroll
        for (int nt = 0; nt < 8; ++nt) {
            sfA[nt][0] = to_tf32(__expf(sfA[nt][0] - nA0));
            sfA[nt][1] = to_tf32(__expf(sfA[nt][1] - nA0));
            sfA[nt][2] = to_tf32(__expf(sfA[nt][2] - nA1));
            sfA[nt][3] = to_tf32(__expf(sfA[nt][3] - nA1));
            sfB[nt][0] = to_tf32(__expf(sfB[nt][0] - nB0));
            sfB[nt][1] = to_tf32(__expf(sfB[nt][1] - nB0));
            sfB[nt][2] = to_tf32(__expf(sfB[nt][2] - nB1));
            sfB[nt][3] = to_tf32(__expf(sfB[nt][3] - nB1));
            sA0 += sfA[nt][0] + sfA[nt][1];
            sA1 += sfA[nt][2] + sfA[nt][3];
            sB0 += sfB[nt][0] + sfB[nt][1];
            sB1 += sfB[nt][2] + sfB[nt][3];
        }
        #pragma unroll
        for (int o2 = 1; o2 <= 2; o2 <<= 1) {
            sA0 += __shfl_xor_sync(0xffffffffu, sA0, o2);
            sA1 += __shfl_xor_sync(0xffffffffu, sA1, o2);
            sB0 += __shfl_xor_sync(0xffffffffu, sB0, o2);
            sB1 += __shfl_xor_sync(0xffffffffu, sB1, o2);
        }
        lA0 = lA0 * cA0 + sA0;
        lA1 = lA1 * cA1 + sA1;
        lB0 = lB0 * cB0 + sB0;
        lB1 = lB1 * cB1 + sB1;

        // ---- O += P @ V (V b-frags shared by both row blocks) --------------
        #pragma unroll
        for (int kt = 0; kt < 8; ++kt) {
            uint32_t aA[4], aB[4];
            {
                const float x00 = __shfl_sync(0xffffffffu, sfA[kt][0], srcA);
                const float x01 = __shfl_sync(0xffffffffu, sfA[kt][1], srcA);
                const float x10 = __shfl_sync(0xffffffffu, sfA[kt][2], srcA);
                const float x11 = __shfl_sync(0xffffffffu, sfA[kt][3], srcA);
                const float y00 = __shfl_sync(0xffffffffu, sfA[kt][0], srcB);
                const float y01 = __shfl_sync(0xffffffffu, sfA[kt][1], srcB);
                const float y10 = __shfl_sync(0xffffffffu, sfA[kt][2], srcB);
                const float y11 = __shfl_sync(0xffffffffu, sfA[kt][3], srcB);
                aA[0] = __float_as_uint(odd ? x01 : x00);
                aA[1] = __float_as_uint(odd ? x11 : x10);
                aA[2] = __float_as_uint(odd ? y01 : y00);
                aA[3] = __float_as_uint(odd ? y11 : y10);
            }
            {
                const float x00 = __shfl_sync(0xffffffffu, sfB[kt][0], srcA);
                const float x01 = __shfl_sync(0xffffffffu, sfB[kt][1], srcA);
                const float x10 = __shfl_sync(0xffffffffu, sfB[kt][2], srcA);
                const float x11 = __shfl_sync(0xffffffffu, sfB[kt][3], srcA);
                const float y00 = __shfl_sync(0xffffffffu, sfB[kt][0], srcB);
                const float y01 = __shfl_sync(0xffffffffu, sfB[kt][1], srcB);
                const float y10 = __shfl_sync(0xffffffffu, sfB[kt][2], srcB);
                const float y11 = __shfl_sync(0xffffffffu, sfB[kt][3], srcB);
                aB[0] = __float_as_uint(odd ? x01 : x00);
                aB[1] = __float_as_uint(odd ? x11 : x10);
                aB[2] = __float_as_uint(odd ? y01 : y00);
                aB[3] = __float_as_uint(odd ? y11 : y10);
            }
            const float* vb0 = V_ + (kt * 8 + g) * kVStride + r;
            const float* vb1 = V_ + (kt * 8 + g + 4) * kVStride + r;
            #pragma unroll
            for (int nt2 = 0; nt2 < 8; ++nt2) {
                uint32_t b[2];
                b[0] = __float_as_uint(vb0[nt2 * 8]);
                b[1] = __float_as_uint(vb1[nt2 * 8]);
                mma_tf32(oA[nt2], aA, b);
                mma_tf32(oB[nt2], aB, b);
            }
        }
        __syncthreads();
    }

    // ---- epilogue ----------------------------------------------------------
    const float iA0 = 1.0f / lA0, iA1 = 1.0f / lA1;
    const float iB0 = 1.0f / lB0, iB1 = 1.0f / lB1;
    const int b = bh >> 4;
    const int h = bh & 15;
    float* dA0 = g_attn + ((size_t)(b * kN + qrow0 + r)) * kDim + h * kD;
    float* dA1 = g_attn + ((size_t)(b * kN + qrow0 + r + 8)) * kDim + h * kD;
    float* dB0 = g_attn + ((size_t)(b * kN + qrow0 + r + 16)) * kDim + h * kD;
    float* dB1 = g_attn + ((size_t)(b * kN + qrow0 + r + 24)) * kDim + h * kD;
    #pragma unroll
    for (int nt2 = 0; nt2 < 8; ++nt2) {
        const int col = nt2 * 8 + 2 * g;
        float2 v;
        v.x = to_tf32(oA[nt2][0] * iA0); v.y = to_tf32(oA[nt2][1] * iA0);
        *reinterpret_cast<float2*>(dA0 + col) = v;
        v.x = to_tf32(oA[nt2][2] * iA1); v.y = to_tf32(oA[nt2][3] * iA1);
        *reinterpret_cast<float2*>(dA1 + col) = v;
        v.x = to_tf32(oB[nt2][0] * iB0); v.y = to_tf32(oB[nt2][1] * iB0);
        *reinterpret_cast<float2*>(dB0 + col) = v;
        v.x = to_tf32(oB[nt2][2] * iB1); v.y = to_tf32(oB[nt2][3] * iB1);
        *reinterpret_cast<float2*>(dB1 + col) = v;
    }
}

// ---------------------------------------------------------------------------
extern "C" void kernel_launch(void* const* d_in, const int* in_sizes, int n_in,
                              void* d_out, int out_size) {
    const float* x     = (const float*)d_in[0];
    const float* gamma = (const float*)d_in[1];
    const float* beta  = (const float*)d_in[2];
    const float* W_qk  = (const float*)d_in[3];
    const float* W_v   = (const float*)d_in[4];
    const float* W_out = (const float*)d_in[5];
    const float* b_out = (const float*)d_in[6];
    float* out = (float*)d_out;

    cudaFuncSetAttribute(gemm_mma<0>, cudaFuncAttributeMaxDynamicSharedMemorySize, kGemmSmemBytes);
    cudaFuncSetAttribute(gemm_mma<1>, cudaFuncAttributeMaxDynamicSharedMemorySize, kGemmSmemBytes);
    cudaFuncSetAttribute(gemm_mma<2>, cudaFuncAttributeMaxDynamicSharedMemorySize, kGemmSmemBytes);
    cudaFuncSetAttribute(attn_mma_kernel, cudaFuncAttributeMaxDynamicSharedMemorySize, kAttnSmemBytes);

    float* wqk_t;  cudaGetSymbolAddress((void**)&wqk_t, g_wqk_t);
    float* wv_t;   cudaGetSymbolAddress((void**)&wv_t, g_wv_t);
    float* wout_t; cudaGetSymbolAddress((void**)&wout_t, g_wout_t);

    ln_kernel<<<kTokens, 256>>>(x, gamma, beta);
    transpose_tf32<<<dim3(kQKCols / 32, kDim / 32), dim3(32, 8)>>>(W_qk, wqk_t, kDim, kQKCols);
    transpose_tf32<<<dim3(kDim / 32, kDim / 32), dim3(32, 8)>>>(W_v, wv_t, kDim, kDim);
    transpose_tf32<<<dim3(kDim / 32, kDim / 32), dim3(32, 8)>>>(W_out, wout_t, kDim, kDim);

    gemm_mma<0><<<dim3(kQKCols / 128, kTokens / 128), 128, kGemmSmemBytes>>>(wqk_t, nullptr, nullptr);
    gemm_mma<1><<<dim3(kDim / 128, kTokens / 128), 128, kGemmSmemBytes>>>(wv_t, nullptr, nullptr);
    attn_mma_kernel<<<dim3(kN / 128, kB * kH), 128, kAttnSmemBytes>>>();
    gemm_mma<2><<<dim3(kDim / 128, kTokens / 128), 128, kGemmSmemBytes>>>(wout_t, out, b_out);
}